// round 2
// baseline (speedup 1.0000x reference)
#include <cuda_runtime.h>
#include <math.h>

#define NB 8
#define NS 2048
#define NE 1024
#define ND 64

// Scratch for Q/K/V projections (allocation-free: static device arrays).
__device__ float g_Q[NB * NS * ND];
__device__ float g_K[NB * NS * ND];
__device__ float g_V[NB * NS * ND];

// ----------------------------------------------------------------------------
// Kernel A: fused QKV projection.
//   Y[m, n] = sum_e x[m, e] * W[n, e] + b[n], with W = [Wq; Wk; Wv] (192 rows).
//   Tile: BM=64 rows x BN=192 cols, BK=16. 256 threads, each 4x12 outputs.
//   x is read exactly once; W (768 KB) stays L2-resident across the 256 CTAs.
// ----------------------------------------------------------------------------
__global__ __launch_bounds__(256) void qkv_kernel(
    const float* __restrict__ x,
    const float* __restrict__ Wq, const float* __restrict__ bq,
    const float* __restrict__ Wk, const float* __restrict__ bk,
    const float* __restrict__ Wv, const float* __restrict__ bv)
{
    __shared__ float As[16][68];    // [k][m], padded
    __shared__ float Bs[16][196];   // [k][n], padded

    const int tid = threadIdx.x;
    const int tx = tid & 15;        // 0..15 -> n block (12 cols each)
    const int ty = tid >> 4;        // 0..15 -> m block (4 rows each)
    const int m0 = blockIdx.x * 64;

    float acc[4][12];
    #pragma unroll
    for (int i = 0; i < 4; i++)
        #pragma unroll
        for (int j = 0; j < 12; j++) acc[i][j] = 0.f;

    for (int k0 = 0; k0 < NE; k0 += 16) {
        // Load A tile: 64x16 = 1024 elems, 4 per thread (16 consecutive threads
        // read 16 consecutive floats -> coalesced 64B segments).
        #pragma unroll
        for (int r = 0; r < 4; r++) {
            int idx = tid + r * 256;
            int row = idx >> 4, col = idx & 15;
            As[col][row] = x[(size_t)(m0 + row) * NE + k0 + col];
        }
        // Load B tile: 192x16 = 3072 elems, 12 per thread.
        #pragma unroll
        for (int r = 0; r < 12; r++) {
            int idx = tid + r * 256;
            int n = idx >> 4, kk = idx & 15;
            const float* W = (n < 64) ? Wq : ((n < 128) ? Wk : Wv);
            Bs[kk][n] = W[(size_t)(n & 63) * NE + k0 + kk];
        }
        __syncthreads();

        #pragma unroll
        for (int k = 0; k < 16; k++) {
            float a[4], bb[12];
            #pragma unroll
            for (int i = 0; i < 4; i++) a[i] = As[k][ty * 4 + i];
            #pragma unroll
            for (int j = 0; j < 12; j++) bb[j] = Bs[k][tx * 12 + j];
            #pragma unroll
            for (int i = 0; i < 4; i++)
                #pragma unroll
                for (int j = 0; j < 12; j++)
                    acc[i][j] = fmaf(a[i], bb[j], acc[i][j]);
        }
        __syncthreads();
    }

    // Epilogue: add bias, scatter to Q/K/V scratch.
    #pragma unroll
    for (int i = 0; i < 4; i++) {
        int m = m0 + ty * 4 + i;
        #pragma unroll
        for (int j = 0; j < 12; j++) {
            int n = tx * 12 + j;
            float bias = (n < 64) ? bq[n] : ((n < 128) ? bk[n - 64] : bv[n - 128]);
            float v = acc[i][j] + bias;
            if (n < 64)       g_Q[(size_t)m * ND + n] = v;
            else if (n < 128) g_K[(size_t)m * ND + (n - 64)] = v;
            else              g_V[(size_t)m * ND + (n - 128)] = v;
        }
    }
}

// ----------------------------------------------------------------------------
// Kernel B: flash attention with anti-causal (j >= i) + key-mask masking.
//   Masked positions get score = -1e22f and stay INSIDE the softmax:
//     - some valid entry in row -> exp(-1e22 - m) underflows to exactly 0
//     - no valid entry in row   -> all scores equal -1e22 -> uniform softmax
//   Both match the jax reference exactly.
//   BR=64 rows x BC=64 cols per tile, 256 threads (16x16), 4x4 register tiles.
//   P tile aliases the K tile (K reads complete before the max-reduce barrier).
// ----------------------------------------------------------------------------
__global__ __launch_bounds__(256) void attn_kernel(
    const int* __restrict__ mask, float* __restrict__ out)
{
    extern __shared__ float smem[];
    float* Qs   = smem;                 // 64*68
    float* Ks   = Qs + 64 * 68;         // 64*68 (aliased by Ps)
    float* Vs   = Ks + 64 * 68;         // 64*68
    float* red  = Vs + 64 * 68;         // 64*16
    float* m_st = red + 64 * 16;        // 64: running row max
    float* l_st = m_st + 64;            // 64: running row sum
    float* al_s = l_st + 64;            // 64: per-row rescale alpha
    int*   mt   = (int*)(al_s + 64);    // 64: mask tile
    float* Ps   = Ks;                   // alias

    const int tid = threadIdx.x;
    const int tx = tid & 15;            // d / col block
    const int ty = tid >> 4;            // row block
    const int b = blockIdx.y;
    const int i0 = blockIdx.x * 64;

    if (tid < 64) { m_st[tid] = -INFINITY; l_st[tid] = 0.f; }

    // Load Q tile (64 rows x 64 d), float4 coalesced.
    #pragma unroll
    for (int p = 0; p < 4; p++) {
        int r = p * 16 + ty;
        *(float4*)&Qs[r * 68 + tx * 4] =
            *(const float4*)&g_Q[((size_t)b * NS + i0 + r) * ND + tx * 4];
    }

    float o[4][4];
    #pragma unroll
    for (int i = 0; i < 4; i++)
        #pragma unroll
        for (int j = 0; j < 4; j++) o[i][j] = 0.f;

    const int gi_base = i0 + ty * 4;

    for (int j0 = 0; j0 < NS; j0 += 64) {
        __syncthreads();  // Qs/m_st ready (iter 0); Ks(=Ps)/Vs free (iter>0)

        #pragma unroll
        for (int p = 0; p < 4; p++) {
            int r = p * 16 + ty;
            *(float4*)&Ks[r * 68 + tx * 4] =
                *(const float4*)&g_K[((size_t)b * NS + j0 + r) * ND + tx * 4];
            *(float4*)&Vs[r * 68 + tx * 4] =
                *(const float4*)&g_V[((size_t)b * NS + j0 + r) * ND + tx * 4];
        }
        if (tid < 64) mt[tid] = mask[b * NS + j0 + tid];
        __syncthreads();

        // ---- S = Q @ K^T (4x4 per thread, float4 smem loads) ----
        float s[4][4];
        #pragma unroll
        for (int i = 0; i < 4; i++)
            #pragma unroll
            for (int j = 0; j < 4; j++) s[i][j] = 0.f;

        #pragma unroll
        for (int d = 0; d < 64; d += 4) {
            float qa[4][4], ka[4][4];
            #pragma unroll
            for (int i = 0; i < 4; i++)
                *(float4*)&qa[i][0] = *(float4*)&Qs[(ty * 4 + i) * 68 + d];
            #pragma unroll
            for (int j = 0; j < 4; j++)
                *(float4*)&ka[j][0] = *(float4*)&Ks[(tx * 4 + j) * 68 + d];
            #pragma unroll
            for (int i = 0; i < 4; i++)
                #pragma unroll
                for (int j = 0; j < 4; j++)
                    #pragma unroll
                    for (int c = 0; c < 4; c++)
                        s[i][j] = fmaf(qa[i][c], ka[j][c], s[i][j]);
        }

        // ---- scale + mask ----
        #pragma unroll
        for (int i = 0; i < 4; i++) {
            int gi = gi_base + i;
            #pragma unroll
            for (int j = 0; j < 4; j++) {
                int gj = j0 + tx * 4 + j;
                bool valid = (gj >= gi) && (mt[tx * 4 + j] != 0);
                s[i][j] = valid ? s[i][j] * 0.125f : -1e22f;
            }
        }

        // ---- row max (partial per thread, then 64-thread reduce) ----
        #pragma unroll
        for (int i = 0; i < 4; i++) {
            float pm = fmaxf(fmaxf(s[i][0], s[i][1]), fmaxf(s[i][2], s[i][3]));
            red[(ty * 4 + i) * 16 + tx] = pm;
        }
        __syncthreads();
        if (tid < 64) {
            const float* rr = &red[tid * 16];
            float mx = rr[0];
            #pragma unroll
            for (int t = 1; t < 16; t++) mx = fmaxf(mx, rr[t]);
            float mo = m_st[tid];
            float mn = fmaxf(mo, mx);   // mx >= -1e22 -> mn always finite
            m_st[tid] = mn;
            al_s[tid] = __expf(mo - mn);  // mo=-inf -> 0 on first tile
        }
        __syncthreads();

        // ---- p = exp(s - m), write P, rescale O, partial row sums ----
        #pragma unroll
        for (int i = 0; i < 4; i++) {
            int r = ty * 4 + i;
            float mn = m_st[r];
            float a  = al_s[r];
            float ps = 0.f;
            #pragma unroll
            for (int j = 0; j < 4; j++) {
                float p = __expf(s[i][j] - mn);
                Ps[r * 68 + tx * 4 + j] = p;
                ps += p;
            }
            #pragma unroll
            for (int j = 0; j < 4; j++) o[i][j] *= a;
            red[r * 16 + tx] = ps;
        }
        __syncthreads();
        if (tid < 64) {
            const float* rr = &red[tid * 16];
            float sum = 0.f;
            #pragma unroll
            for (int t = 0; t < 16; t++) sum += rr[t];
            l_st[tid] = l_st[tid] * al_s[tid] + sum;
        }

        // ---- O += P @ V ----
        #pragma unroll
        for (int c = 0; c < 64; c += 4) {
            float pa[4][4], va[4][4];
            #pragma unroll
            for (int i = 0; i < 4; i++)
                *(float4*)&pa[i][0] = *(float4*)&Ps[(ty * 4 + i) * 68 + c];
            #pragma unroll
            for (int cc = 0; cc < 4; cc++)
                *(float4*)&va[cc][0] = *(float4*)&Vs[(c + cc) * 68 + tx * 4];
            #pragma unroll
            for (int i = 0; i < 4; i++)
                #pragma unroll
                for (int dd = 0; dd < 4; dd++)
                    #pragma unroll
                    for (int cc = 0; cc < 4; cc++)
                        o[i][dd] = fmaf(pa[i][cc], va[cc][dd], o[i][dd]);
        }
    }

    __syncthreads();  // l_st final values visible

    #pragma unroll
    for (int i = 0; i < 4; i++) {
        int r = ty * 4 + i;
        float inv = 1.0f / l_st[r];
        float4 v;
        v.x = o[i][0] * inv; v.y = o[i][1] * inv;
        v.z = o[i][2] * inv; v.w = o[i][3] * inv;
        *(float4*)&out[((size_t)b * NS + i0 + r) * ND + tx * 4] = v;
    }
}

// ----------------------------------------------------------------------------
// Launch: QKV projection then flash attention (same stream, serialized).
// ----------------------------------------------------------------------------
extern "C" void kernel_launch(void* const* d_in, const int* in_sizes, int n_in,
                              void* d_out, int out_size)
{
    const float* x    = (const float*)d_in[0];
    const int*   mask = (const int*)  d_in[1];
    const float* Wq   = (const float*)d_in[2];
    const float* bq   = (const float*)d_in[3];
    const float* Wk   = (const float*)d_in[4];
    const float* bk   = (const float*)d_in[5];
    const float* Wv   = (const float*)d_in[6];
    const float* bv   = (const float*)d_in[7];
    float* out = (float*)d_out;

    qkv_kernel<<<(NB * NS) / 64, 256>>>(x, Wq, bq, Wk, bk, Wv, bv);

    // Dynamic smem: 3*64*68 + 64*16 + 3*64 floats + 64 ints = 57344 bytes
    const int SMEM_BYTES = (3 * 64 * 68 + 64 * 16 + 3 * 64) * 4 + 64 * 4;
    cudaFuncSetAttribute(attn_kernel,
                         cudaFuncAttributeMaxDynamicSharedMemorySize, SMEM_BYTES);
    dim3 grid(NS / 64, NB);
    attn_kernel<<<grid, 256, SMEM_BYTES>>>(mask, out);
}

// round 5
// speedup vs baseline: 1.4571x; 1.4571x over previous
#include <cuda_runtime.h>
#include <math.h>

#define NB 8
#define NS 2048
#define NE 1024
#define ND 64

// Scratch (allocation-free: static device arrays, zero-initialized at load).
__device__ float g_Q[NB * NS * ND];
__device__ float g_K[NB * NS * ND];
__device__ float g_V[NB * NS * ND];
__device__ int   g_js[NB * NS];      // per-batch sorted valid column indices
__device__ int   g_Nv[NB];           // per-batch valid column count
__device__ float g_Vmean[NB * ND];   // per-batch column-mean of V (all rows)

// ----------------------------------------------------------------------------
// Kernel A: fused QKV projection (unchanged from R1 — proven at ~180us).
// ----------------------------------------------------------------------------
__global__ __launch_bounds__(256) void qkv_kernel(
    const float* __restrict__ x,
    const float* __restrict__ Wq, const float* __restrict__ bq,
    const float* __restrict__ Wk, const float* __restrict__ bk,
    const float* __restrict__ Wv, const float* __restrict__ bv)
{
    __shared__ float As[16][68];
    __shared__ float Bs[16][196];

    const int tid = threadIdx.x;
    const int tx = tid & 15;
    const int ty = tid >> 4;
    const int m0 = blockIdx.x * 64;

    float acc[4][12];
    #pragma unroll
    for (int i = 0; i < 4; i++)
        #pragma unroll
        for (int j = 0; j < 12; j++) acc[i][j] = 0.f;

    for (int k0 = 0; k0 < NE; k0 += 16) {
        #pragma unroll
        for (int r = 0; r < 4; r++) {
            int idx = tid + r * 256;
            int row = idx >> 4, col = idx & 15;
            As[col][row] = x[(size_t)(m0 + row) * NE + k0 + col];
        }
        #pragma unroll
        for (int r = 0; r < 12; r++) {
            int idx = tid + r * 256;
            int n = idx >> 4, kk = idx & 15;
            const float* W = (n < 64) ? Wq : ((n < 128) ? Wk : Wv);
            Bs[kk][n] = W[(size_t)(n & 63) * NE + k0 + kk];
        }
        __syncthreads();

        #pragma unroll
        for (int k = 0; k < 16; k++) {
            float a[4], bb[12];
            #pragma unroll
            for (int i = 0; i < 4; i++) a[i] = As[k][ty * 4 + i];
            #pragma unroll
            for (int j = 0; j < 12; j++) bb[j] = Bs[k][tx * 12 + j];
            #pragma unroll
            for (int i = 0; i < 4; i++)
                #pragma unroll
                for (int j = 0; j < 12; j++)
                    acc[i][j] = fmaf(a[i], bb[j], acc[i][j]);
        }
        __syncthreads();
    }

    #pragma unroll
    for (int i = 0; i < 4; i++) {
        int m = m0 + ty * 4 + i;
        #pragma unroll
        for (int j = 0; j < 12; j++) {
            int n = tx * 12 + j;
            float bias = (n < 64) ? bq[n] : ((n < 128) ? bk[n - 64] : bv[n - 128]);
            float v = acc[i][j] + bias;
            if (n < 64)       g_Q[(size_t)m * ND + n] = v;
            else if (n < 128) g_K[(size_t)m * ND + (n - 64)] = v;
            else              g_V[(size_t)m * ND + (n - 128)] = v;
        }
    }
}

// ----------------------------------------------------------------------------
// Kernel P: per-batch prep.
//   (1) prefix-scan mask -> sorted valid column index list g_js + count g_Nv
//   (2) g_Vmean[b][:] = mean over ALL 2048 rows of V (for fully-masked rows:
//       reference softmax of an all-equal row is uniform -> output = mean(V)).
// ----------------------------------------------------------------------------
__global__ __launch_bounds__(256) void prep_kernel(const int* __restrict__ mask)
{
    const int b = blockIdx.x;
    const int tid = threadIdx.x;
    __shared__ int ps[257];
    __shared__ float vred[256];

    // Each thread scans 8 mask entries.
    const int base = tid * 8;
    int loc[8], cnt = 0;
    #pragma unroll
    for (int u = 0; u < 8; u++) {
        loc[u] = mask[b * NS + base + u];
        cnt += (loc[u] != 0);
    }
    ps[tid + 1] = cnt;
    __syncthreads();
    if (tid == 0) {
        ps[0] = 0;
        for (int t = 1; t <= 256; t++) ps[t] += ps[t - 1];
    }
    __syncthreads();

    int pos = ps[tid];
    #pragma unroll
    for (int u = 0; u < 8; u++) {
        if (loc[u] != 0) g_js[b * NS + pos++] = base + u;
    }
    if (tid == 0) g_Nv[b] = ps[256];

    // V column-mean: thread handles column d = tid&63 over a 512-row segment.
    const int d = tid & 63;
    const int seg = tid >> 6;
    float s = 0.f;
    const float* Vb = &g_V[(size_t)b * NS * ND];
    for (int r = seg * 512; r < seg * 512 + 512; r++)
        s += Vb[(size_t)r * ND + d];
    vred[tid] = s;
    __syncthreads();
    if (tid < 64) {
        float t = vred[tid] + vred[tid + 64] + vred[tid + 128] + vred[tid + 192];
        g_Vmean[b * ND + tid] = t * (1.0f / NS);
    }
}

// ----------------------------------------------------------------------------
// Kernel B: flash attention over COMPACTED valid columns + triangle tile skip.
//   - Only columns with mask=1 are visited (indirected via g_js; rows stay
//     256B-contiguous so coalescing is unchanged).
//   - Tiles whose max original index < i0 are skipped (anti-causal: j >= i).
//     Exact: exp(-1e22 - m) == 0 in fp32 whenever the row has a real entry.
//   - Rows that never see a valid entry keep m <= -1e21 sentinel -> output
//     overridden with precomputed V-mean (== reference uniform softmax).
//   - 1/sqrt(D)=0.125 folded into Q at load (power of two: exact).
// ----------------------------------------------------------------------------
__global__ __launch_bounds__(256) void attn_kernel(float* __restrict__ out)
{
    extern __shared__ float smem[];
    float* Qs   = smem;                 // 64*68
    float* Ks   = Qs + 64 * 68;         // 64*68 (aliased by Ps)
    float* Vs   = Ks + 64 * 68;         // 64*68
    float* red  = Vs + 64 * 68;         // 64*16
    float* m_st = red + 64 * 16;        // 64
    float* l_st = m_st + 64;            // 64
    float* al_s = l_st + 64;            // 64
    int*   js_s = (int*)(al_s + 64);    // 64: original column indices of tile
    float* Ps   = Ks;                   // alias

    const int tid = threadIdx.x;
    const int tx = tid & 15;
    const int ty = tid >> 4;
    const int b = blockIdx.y;
    const int i0 = blockIdx.x * 64;

    const int Nv = g_Nv[b];
    const int ntiles = (Nv + 63) >> 6;

    if (tid < 64) { m_st[tid] = -INFINITY; l_st[tid] = 0.f; }

    // Load Q tile, pre-scaled by 0.125 (exact power-of-two scaling).
    #pragma unroll
    for (int p = 0; p < 4; p++) {
        int r = p * 16 + ty;
        float4 q = *(const float4*)&g_Q[((size_t)b * NS + i0 + r) * ND + tx * 4];
        q.x *= 0.125f; q.y *= 0.125f; q.z *= 0.125f; q.w *= 0.125f;
        *(float4*)&Qs[r * 68 + tx * 4] = q;
    }

    float o[4][4];
    #pragma unroll
    for (int i = 0; i < 4; i++)
        #pragma unroll
        for (int j = 0; j < 4; j++) o[i][j] = 0.f;

    const int gi_base = i0 + ty * 4;

    for (int jt = 0; jt < ntiles; jt++) {
        const int j0c = jt * 64;
        __syncthreads();  // prev-iter Ps reads done; (iter 0) Qs/m_st ready

        if (tid < 64) {
            int c = j0c + tid;
            js_s[tid] = (c < Nv) ? g_js[b * NS + c] : -1;
        }
        __syncthreads();

        // Triangle skip: compacted indices ascend; if the tile's last real
        // index is < i0 no element can satisfy j >= i for this row block.
        const int cnt = min(64, Nv - j0c);
        if (js_s[cnt - 1] < i0) continue;

        // Load K/V tiles through the index list (padded rows read row 0,
        // killed later by the js < 0 predicate).
        #pragma unroll
        for (int p = 0; p < 4; p++) {
            int r = p * 16 + ty;
            int src = js_s[r];
            if (src < 0) src = 0;
            *(float4*)&Ks[r * 68 + tx * 4] =
                *(const float4*)&g_K[((size_t)b * NS + src) * ND + tx * 4];
            *(float4*)&Vs[r * 68 + tx * 4] =
                *(const float4*)&g_V[((size_t)b * NS + src) * ND + tx * 4];
        }
        __syncthreads();

        // ---- S = Q @ K^T ----
        float s[4][4];
        #pragma unroll
        for (int i = 0; i < 4; i++)
            #pragma unroll
            for (int j = 0; j < 4; j++) s[i][j] = 0.f;

        #pragma unroll
        for (int d = 0; d < 64; d += 4) {
            float qa[4][4], ka[4][4];
            #pragma unroll
            for (int i = 0; i < 4; i++)
                *(float4*)&qa[i][0] = *(float4*)&Qs[(ty * 4 + i) * 68 + d];
            #pragma unroll
            for (int j = 0; j < 4; j++)
                *(float4*)&ka[j][0] = *(float4*)&Ks[(tx * 4 + j) * 68 + d];
            #pragma unroll
            for (int i = 0; i < 4; i++)
                #pragma unroll
                for (int j = 0; j < 4; j++)
                    #pragma unroll
                    for (int c = 0; c < 4; c++)
                        s[i][j] = fmaf(qa[i][c], ka[j][c], s[i][j]);
        }

        // ---- mask (scale already folded into Q) ----
        #pragma unroll
        for (int i = 0; i < 4; i++) {
            int gi = gi_base + i;
            #pragma unroll
            for (int j = 0; j < 4; j++) {
                bool valid = (js_s[tx * 4 + j] >= gi);
                s[i][j] = valid ? s[i][j] : -1e22f;
            }
        }

        // ---- row max ----
        #pragma unroll
        for (int i = 0; i < 4; i++) {
            float pm = fmaxf(fmaxf(s[i][0], s[i][1]), fmaxf(s[i][2], s[i][3]));
            red[(ty * 4 + i) * 16 + tx] = pm;
        }
        __syncthreads();
        if (tid < 64) {
            const float* rr = &red[tid * 16];
            float mx = rr[0];
            #pragma unroll
            for (int t = 1; t < 16; t++) mx = fmaxf(mx, rr[t]);
            float mo = m_st[tid];
            float mn = fmaxf(mo, mx);
            m_st[tid] = mn;
            al_s[tid] = __expf(mo - mn);  // -inf -> 0 on first processed tile
        }
        __syncthreads();

        // ---- p = exp(s - m), write P (aliases K), rescale O, row sums ----
        #pragma unroll
        for (int i = 0; i < 4; i++) {
            int r = ty * 4 + i;
            float mn = m_st[r];
            float a  = al_s[r];
            float psum = 0.f;
            #pragma unroll
            for (int j = 0; j < 4; j++) {
                float p = __expf(s[i][j] - mn);
                Ps[r * 68 + tx * 4 + j] = p;
                psum += p;
            }
            #pragma unroll
            for (int j = 0; j < 4; j++) o[i][j] *= a;
            red[r * 16 + tx] = psum;
        }
        __syncthreads();
        if (tid < 64) {
            const float* rr = &red[tid * 16];
            float sum = 0.f;
            #pragma unroll
            for (int t = 0; t < 16; t++) sum += rr[t];
            l_st[tid] = l_st[tid] * al_s[tid] + sum;
        }

        // ---- O += P @ V ----
        #pragma unroll
        for (int c = 0; c < 64; c += 4) {
            float pa[4][4], va[4][4];
            #pragma unroll
            for (int i = 0; i < 4; i++)
                *(float4*)&pa[i][0] = *(float4*)&Ps[(ty * 4 + i) * 68 + c];
            #pragma unroll
            for (int cc = 0; cc < 4; cc++)
                *(float4*)&va[cc][0] = *(float4*)&Vs[(c + cc) * 68 + tx * 4];
            #pragma unroll
            for (int i = 0; i < 4; i++)
                #pragma unroll
                for (int dd = 0; dd < 4; dd++)
                    #pragma unroll
                    for (int cc = 0; cc < 4; cc++)
                        o[i][dd] = fmaf(pa[i][cc], va[cc][dd], o[i][dd]);
        }
    }

    __syncthreads();  // final l_st / m_st visible

    #pragma unroll
    for (int i = 0; i < 4; i++) {
        int r = ty * 4 + i;
        if (m_st[r] <= -1e21f) {
            // Row never saw a valid (masked, j>=i) entry: reference softmax is
            // uniform over ALL 2048 columns -> output = column-mean of V.
            *(float4*)&out[((size_t)b * NS + i0 + r) * ND + tx * 4] =
                *(const float4*)&g_Vmean[b * ND + tx * 4];
        } else {
            float inv = 1.0f / l_st[r];
            float4 v;
            v.x = o[i][0] * inv; v.y = o[i][1] * inv;
            v.z = o[i][2] * inv; v.w = o[i][3] * inv;
            *(float4*)&out[((size_t)b * NS + i0 + r) * ND + tx * 4] = v;
        }
    }
}

// ----------------------------------------------------------------------------
// Launch: QKV projection -> prep (compaction + V-mean) -> flash attention.
// ----------------------------------------------------------------------------
extern "C" void kernel_launch(void* const* d_in, const int* in_sizes, int n_in,
                              void* d_out, int out_size)
{
    const float* x    = (const float*)d_in[0];
    const int*   mask = (const int*)  d_in[1];
    const float* Wq   = (const float*)d_in[2];
    const float* bq   = (const float*)d_in[3];
    const float* Wk   = (const float*)d_in[4];
    const float* bk   = (const float*)d_in[5];
    const float* Wv   = (const float*)d_in[6];
    const float* bv   = (const float*)d_in[7];
    float* out = (float*)d_out;

    qkv_kernel<<<(NB * NS) / 64, 256>>>(x, Wq, bq, Wk, bk, Wv, bv);
    prep_kernel<<<NB, 256>>>(mask);

    const int SMEM_BYTES = (3 * 64 * 68 + 64 * 16 + 3 * 64) * 4 + 64 * 4;
    cudaFuncSetAttribute(attn_kernel,
                         cudaFuncAttributeMaxDynamicSharedMemorySize, SMEM_BYTES);
    dim3 grid(NS / 64, NB);
    attn_kernel<<<grid, 256, SMEM_BYTES>>>(out);
}

// round 12
// speedup vs baseline: 1.7578x; 1.2063x over previous
#include <cuda_runtime.h>
#include <math.h>

#define NB 8
#define NS 2048
#define NE 1024
#define ND 64
#define NSPLIT 2

// ---------------------------------------------------------------------------
// Static device scratch (allocation-free).
// ---------------------------------------------------------------------------
__device__ float g_Q[NB * NS * ND];
__device__ float g_K[NB * NS * ND];
__device__ float g_V[NB * NS * ND];
__device__ int   g_js[NB * NS];
__device__ int   g_Nv[NB];
__device__ float g_Vmean[NB * ND];
// Split-KV partials (unnormalized O, running max m, running sum l).
__device__ float g_OP[NSPLIT][(size_t)NB * NS * ND];
__device__ float g_mP[NSPLIT][NB * NS];
__device__ float g_lP[NSPLIT][NB * NS];

// ----------------------------------------------------------------------------
// Kernel A: fused QKV projection (proven at ~186us — unchanged).
// ----------------------------------------------------------------------------
__global__ __launch_bounds__(256) void qkv_kernel(
    const float* __restrict__ x,
    const float* __restrict__ Wq, const float* __restrict__ bq,
    const float* __restrict__ Wk, const float* __restrict__ bk,
    const float* __restrict__ Wv, const float* __restrict__ bv)
{
    __shared__ float As[16][68];
    __shared__ float Bs[16][196];

    const int tid = threadIdx.x;
    const int tx = tid & 15;
    const int ty = tid >> 4;
    const int m0 = blockIdx.x * 64;

    float acc[4][12];
    #pragma unroll
    for (int i = 0; i < 4; i++)
        #pragma unroll
        for (int j = 0; j < 12; j++) acc[i][j] = 0.f;

    for (int k0 = 0; k0 < NE; k0 += 16) {
        #pragma unroll
        for (int r = 0; r < 4; r++) {
            int idx = tid + r * 256;
            int row = idx >> 4, col = idx & 15;
            As[col][row] = x[(size_t)(m0 + row) * NE + k0 + col];
        }
        #pragma unroll
        for (int r = 0; r < 12; r++) {
            int idx = tid + r * 256;
            int n = idx >> 4, kk = idx & 15;
            const float* W = (n < 64) ? Wq : ((n < 128) ? Wk : Wv);
            Bs[kk][n] = W[(size_t)(n & 63) * NE + k0 + kk];
        }
        __syncthreads();

        #pragma unroll
        for (int k = 0; k < 16; k++) {
            float a[4], bb[12];
            #pragma unroll
            for (int i = 0; i < 4; i++) a[i] = As[k][ty * 4 + i];
            #pragma unroll
            for (int j = 0; j < 12; j++) bb[j] = Bs[k][tx * 12 + j];
            #pragma unroll
            for (int i = 0; i < 4; i++)
                #pragma unroll
                for (int j = 0; j < 12; j++)
                    acc[i][j] = fmaf(a[i], bb[j], acc[i][j]);
        }
        __syncthreads();
    }

    #pragma unroll
    for (int i = 0; i < 4; i++) {
        int m = m0 + ty * 4 + i;
        #pragma unroll
        for (int j = 0; j < 12; j++) {
            int n = tx * 12 + j;
            float bias = (n < 64) ? bq[n] : ((n < 128) ? bk[n - 64] : bv[n - 128]);
            float v = acc[i][j] + bias;
            if (n < 64)       g_Q[(size_t)m * ND + n] = v;
            else if (n < 128) g_K[(size_t)m * ND + (n - 64)] = v;
            else              g_V[(size_t)m * ND + (n - 128)] = v;
        }
    }
}

// ----------------------------------------------------------------------------
// Kernel P: per-batch prep (mask compaction + V column-mean). Unchanged.
// ----------------------------------------------------------------------------
__global__ __launch_bounds__(256) void prep_kernel(const int* __restrict__ mask)
{
    const int b = blockIdx.x;
    const int tid = threadIdx.x;
    __shared__ int ps[257];
    __shared__ float vred[256];

    const int base = tid * 8;
    int loc[8], cnt = 0;
    #pragma unroll
    for (int u = 0; u < 8; u++) {
        loc[u] = mask[b * NS + base + u];
        cnt += (loc[u] != 0);
    }
    ps[tid + 1] = cnt;
    __syncthreads();
    if (tid == 0) {
        ps[0] = 0;
        for (int t = 1; t <= 256; t++) ps[t] += ps[t - 1];
    }
    __syncthreads();

    int pos = ps[tid];
    #pragma unroll
    for (int u = 0; u < 8; u++) {
        if (loc[u] != 0) g_js[b * NS + pos++] = base + u;
    }
    if (tid == 0) g_Nv[b] = ps[256];

    const int d = tid & 63;
    const int seg = tid >> 6;
    float s = 0.f;
    const float* Vb = &g_V[(size_t)b * NS * ND];
    for (int r = seg * 512; r < seg * 512 + 512; r++)
        s += Vb[(size_t)r * ND + d];
    vred[tid] = s;
    __syncthreads();
    if (tid < 64) {
        float t = vred[tid] + vred[tid + 64] + vred[tid + 128] + vred[tid + 192];
        g_Vmean[b * ND + tid] = t * (1.0f / NS);
    }
}

// ----------------------------------------------------------------------------
// Kernel B: split-KV flash attention over compacted valid columns.
//   Valid tiles for row-block i0 form a suffix [jt0, ntiles) of the compacted
//   list (indices sorted ascending). blockIdx.z selects which half of that
//   suffix this CTA processes; partials (m, l, unnormalized O) go to scratch.
// ----------------------------------------------------------------------------
__global__ __launch_bounds__(256) void attn_kernel()
{
    extern __shared__ float fsm[];
    float* Qs   = fsm;                  // 64*68
    float* Ks   = Qs + 64 * 68;         // 64*68 (aliased by Ps)
    float* Vs   = Ks + 64 * 68;         // 64*68
    float* red  = Vs + 64 * 68;         // 64*16
    float* m_st = red + 64 * 16;        // 64
    float* l_st = m_st + 64;            // 64
    float* al_s = l_st + 64;            // 64
    int*   js_s = (int*)(al_s + 64);    // 64
    float* Ps   = Ks;                   // alias

    const int tid = threadIdx.x;
    const int tx = tid & 15;
    const int ty = tid >> 4;
    const int b  = blockIdx.y;
    const int i0 = blockIdx.x * 64;
    const int sp = blockIdx.z;

    const int Nv = g_Nv[b];
    const int ntiles = (Nv + 63) >> 6;

    // Binary search: first compacted position with index >= i0 -> suffix start.
    int lo = 0, hi = Nv;
    while (lo < hi) {
        int mid = (lo + hi) >> 1;
        if (g_js[b * NS + mid] < i0) lo = mid + 1; else hi = mid;
    }
    const int jt0 = lo >> 6;
    const int nav = ntiles - jt0;
    const int nh  = (nav + 1) >> 1;
    const int t_begin = jt0 + sp * nh;
    const int t_end   = sp ? ntiles : (jt0 + nh);

    if (tid < 64) { m_st[tid] = -INFINITY; l_st[tid] = 0.f; }

    // Load Q tile, pre-scaled by 0.125 (exact power-of-two).
    #pragma unroll
    for (int p = 0; p < 4; p++) {
        int r = p * 16 + ty;
        float4 q = *(const float4*)&g_Q[((size_t)b * NS + i0 + r) * ND + tx * 4];
        q.x *= 0.125f; q.y *= 0.125f; q.z *= 0.125f; q.w *= 0.125f;
        *(float4*)&Qs[r * 68 + tx * 4] = q;
    }

    float o[4][4];
    #pragma unroll
    for (int i = 0; i < 4; i++)
        #pragma unroll
        for (int j = 0; j < 4; j++) o[i][j] = 0.f;

    const int gi_base = i0 + ty * 4;

    for (int jt = t_begin; jt < t_end; jt++) {
        const int j0c = jt * 64;
        __syncthreads();  // prev Ps reads done; (first iter) Qs/m_st ready

        if (tid < 64) {
            int c = j0c + tid;
            js_s[tid] = (c < Nv) ? g_js[b * NS + c] : -1;
        }
        __syncthreads();

        #pragma unroll
        for (int p = 0; p < 4; p++) {
            int r = p * 16 + ty;
            int src = js_s[r];
            if (src < 0) src = 0;
            *(float4*)&Ks[r * 68 + tx * 4] =
                *(const float4*)&g_K[((size_t)b * NS + src) * ND + tx * 4];
            *(float4*)&Vs[r * 68 + tx * 4] =
                *(const float4*)&g_V[((size_t)b * NS + src) * ND + tx * 4];
        }
        __syncthreads();

        // ---- S = Q @ K^T ----
        float s[4][4];
        #pragma unroll
        for (int i = 0; i < 4; i++)
            #pragma unroll
            for (int j = 0; j < 4; j++) s[i][j] = 0.f;

        #pragma unroll
        for (int d = 0; d < 64; d += 4) {
            float qa[4][4], ka[4][4];
            #pragma unroll
            for (int i = 0; i < 4; i++)
                *(float4*)&qa[i][0] = *(float4*)&Qs[(ty * 4 + i) * 68 + d];
            #pragma unroll
            for (int j = 0; j < 4; j++)
                *(float4*)&ka[j][0] = *(float4*)&Ks[(tx * 4 + j) * 68 + d];
            #pragma unroll
            for (int i = 0; i < 4; i++)
                #pragma unroll
                for (int j = 0; j < 4; j++)
                    #pragma unroll
                    for (int cc = 0; cc < 4; cc++)
                        s[i][j] = fmaf(qa[i][cc], ka[j][cc], s[i][j]);
        }

        // ---- mask (scale folded into Q) ----
        #pragma unroll
        for (int i = 0; i < 4; i++) {
            int gi = gi_base + i;
            #pragma unroll
            for (int j = 0; j < 4; j++) {
                bool valid = (js_s[tx * 4 + j] >= gi);
                s[i][j] = valid ? s[i][j] : -1e22f;
            }
        }

        // ---- row max ----
        #pragma unroll
        for (int i = 0; i < 4; i++) {
            float pm = fmaxf(fmaxf(s[i][0], s[i][1]), fmaxf(s[i][2], s[i][3]));
            red[(ty * 4 + i) * 16 + tx] = pm;
        }
        __syncthreads();
        if (tid < 64) {
            const float* rr = &red[tid * 16];
            float mx = rr[0];
            #pragma unroll
            for (int t = 1; t < 16; t++) mx = fmaxf(mx, rr[t]);
            float mo = m_st[tid];
            float mn = fmaxf(mo, mx);
            m_st[tid] = mn;
            al_s[tid] = __expf(mo - mn);
        }
        __syncthreads();

        // ---- p = exp(s - m), write P (aliases K), rescale O, row sums ----
        #pragma unroll
        for (int i = 0; i < 4; i++) {
            int r = ty * 4 + i;
            float mn = m_st[r];
            float a  = al_s[r];
            float psum = 0.f;
            #pragma unroll
            for (int j = 0; j < 4; j++) {
                float p = __expf(s[i][j] - mn);
                Ps[r * 68 + tx * 4 + j] = p;
                psum += p;
            }
            #pragma unroll
            for (int j = 0; j < 4; j++) o[i][j] *= a;
            red[r * 16 + tx] = psum;
        }
        __syncthreads();
        if (tid < 64) {
            const float* rr = &red[tid * 16];
            float sum = 0.f;
            #pragma unroll
            for (int t = 0; t < 16; t++) sum += rr[t];
            l_st[tid] = l_st[tid] * al_s[tid] + sum;
        }

        // ---- O += P @ V ----
        #pragma unroll
        for (int cc = 0; cc < 64; cc += 4) {
            float pa[4][4], va[4][4];
            #pragma unroll
            for (int i = 0; i < 4; i++)
                *(float4*)&pa[i][0] = *(float4*)&Ps[(ty * 4 + i) * 68 + cc];
            #pragma unroll
            for (int k2 = 0; k2 < 4; k2++)
                *(float4*)&va[k2][0] = *(float4*)&Vs[(cc + k2) * 68 + tx * 4];
            #pragma unroll
            for (int i = 0; i < 4; i++)
                #pragma unroll
                for (int dd = 0; dd < 4; dd++)
                    #pragma unroll
                    for (int k2 = 0; k2 < 4; k2++)
                        o[i][dd] = fmaf(pa[i][k2], va[k2][dd], o[i][dd]);
        }
    }

    __syncthreads();  // final m_st/l_st visible (also required if 0 iterations)

    // Emit partials (unnormalized O, m, l). Empty split -> m=-inf, l=0, O=0.
    #pragma unroll
    for (int i = 0; i < 4; i++) {
        int r = ty * 4 + i;
        float4 v;
        v.x = o[i][0]; v.y = o[i][1]; v.z = o[i][2]; v.w = o[i][3];
        *(float4*)&g_OP[sp][((size_t)b * NS + i0 + r) * ND + tx * 4] = v;
    }
    if (tid < 64) {
        g_mP[sp][b * NS + i0 + tid] = m_st[tid];
        g_lP[sp][b * NS + i0 + tid] = l_st[tid];
    }
}

// ----------------------------------------------------------------------------
// Kernel M: merge the two split-KV partials.
//   m=max(m0,m1); O=(O0*e^{m0-m}+O1*e^{m1-m})/(l0*e^{m0-m}+l1*e^{m1-m}).
//   Degenerates handled exactly: empty split (m=-inf) and all-invalid split
//   (m=-1e22) both get weight exp(<=-1e21)==0; fully-dead rows (m<=-1e21)
//   take the reference's uniform-softmax path -> Vmean.
// ----------------------------------------------------------------------------
__global__ __launch_bounds__(256) void merge_kernel(float* __restrict__ out)
{
    const int idx = blockIdx.x * 256 + threadIdx.x;   // one float4 each
    const int row = idx >> 4;                          // 0 .. NB*NS-1
    const int c   = (idx & 15) * 4;
    const int b   = row >> 11;                         // row / NS

    const float m0 = g_mP[0][row];
    const float m1 = g_mP[1][row];
    const float m  = fmaxf(m0, m1);

    float4 r;
    if (m <= -1e21f) {
        r = *(const float4*)&g_Vmean[b * ND + c];
    } else {
        const float e0 = __expf(m0 - m);
        const float e1 = __expf(m1 - m);
        const float l  = g_lP[0][row] * e0 + g_lP[1][row] * e1;
        const float inv = 1.0f / l;
        const float4 a  = *(const float4*)&g_OP[0][(size_t)row * ND + c];
        const float4 bb = *(const float4*)&g_OP[1][(size_t)row * ND + c];
        r.x = (a.x * e0 + bb.x * e1) * inv;
        r.y = (a.y * e0 + bb.y * e1) * inv;
        r.z = (a.z * e0 + bb.z * e1) * inv;
        r.w = (a.w * e0 + bb.w * e1) * inv;
    }
    *(float4*)&out[(size_t)row * ND + c] = r;
}

// ----------------------------------------------------------------------------
// Launch: QKV -> prep -> split-KV attention -> merge.
// ----------------------------------------------------------------------------
extern "C" void kernel_launch(void* const* d_in, const int* in_sizes, int n_in,
                              void* d_out, int out_size)
{
    const float* x    = (const float*)d_in[0];
    const int*   mask = (const int*)  d_in[1];
    const float* Wq   = (const float*)d_in[2];
    const float* bq   = (const float*)d_in[3];
    const float* Wk   = (const float*)d_in[4];
    const float* bk   = (const float*)d_in[5];
    const float* Wv   = (const float*)d_in[6];
    const float* bv   = (const float*)d_in[7];
    float* out = (float*)d_out;

    qkv_kernel<<<(NB * NS) / 64, 256>>>(x, Wq, bq, Wk, bk, Wv, bv);
    prep_kernel<<<NB, 256>>>(mask);

    const int ATTN_SMEM = (3 * 64 * 68 + 64 * 16 + 3 * 64) * 4 + 64 * 4;
    cudaFuncSetAttribute(attn_kernel,
                         cudaFuncAttributeMaxDynamicSharedMemorySize, ATTN_SMEM);
    dim3 grid(NS / 64, NB, NSPLIT);
    attn_kernel<<<grid, 256, ATTN_SMEM>>>();

    merge_kernel<<<(NB * NS * ND / 4) / 256, 256>>>(out);
}